// round 8
// baseline (speedup 1.0000x reference)
#include <cuda_runtime.h>
#include <cuda_bf16.h>
#include <math.h>
#include <stdint.h>

// ---------------------------------------------------------------------------
// GCN 2-layer forward. R8: GEMM1 HMMA with ldmatrix fragment loads; launch
// order rearranged so ncu (-s 5 -c 1) profiles k_gemm1_mma.
// ---------------------------------------------------------------------------

#define NMAX 100000
#define EMAX 1600000
#define FIN  512
#define HID  128
#define NCLS 40
#define NBLK ((NMAX + 1023) / 1024)

typedef unsigned long long ull;

// --------------------------- device scratch --------------------------------
__device__ int   g_is64;
__device__ int   g_cnt[NMAX];
__device__ int   g_off[NMAX + 1];
__device__ int   g_cur[NMAX];
__device__ float g_dis[NMAX];
__device__ int   g_blksum[NBLK];
__device__ int   g_blkoff[NBLK];
__device__ int   g_esrc[EMAX];
__device__ float g_enrm[EMAX];
__device__ __align__(128) __nv_bfloat16 g_w1h[(size_t)HID * FIN];  // W1^T hi
__device__ __align__(128) __nv_bfloat16 g_w1l[(size_t)HID * FIN];  // W1^T lo
__device__ __align__(128) float g_h1[(size_t)NMAX * HID];
__device__ __align__(128) float g_a1[(size_t)NMAX * HID];
__device__ __align__(128) float g_h2[(size_t)NMAX * NCLS];

// --------------------------- helpers ---------------------------------------
__device__ __forceinline__ int load_idx(const int* __restrict__ p, long long slot, int is64) {
    return is64 ? p[2 * slot] : p[slot];
}
__global__ void k_probe(const unsigned* __restrict__ p) {
    unsigned nz = 0;
    for (int i = 1; i < 256; i += 2) nz |= p[i];
    g_is64 = (nz == 0u) ? 1 : 0;
}

__device__ __forceinline__ unsigned pack_hi2(float x, float y) {
    __nv_bfloat16 hx = __float2bfloat16(x), hy = __float2bfloat16(y);
    return (unsigned)__bfloat16_as_ushort(hx) | ((unsigned)__bfloat16_as_ushort(hy) << 16);
}
__device__ __forceinline__ unsigned pack_lo2(float x, float y) {
    __nv_bfloat16 hx = __float2bfloat16(x), hy = __float2bfloat16(y);
    __nv_bfloat16 lx = __float2bfloat16(x - __bfloat162float(hx));
    __nv_bfloat16 ly = __float2bfloat16(y - __bfloat162float(hy));
    return (unsigned)__bfloat16_as_ushort(lx) | ((unsigned)__bfloat16_as_ushort(ly) << 16);
}
__device__ __forceinline__ uint32_t smem_u32(const void* p) {
    uint32_t a;
    asm("{ .reg .u64 t; cvta.to.shared.u64 t, %1; cvt.u32.u64 %0, t; }" : "=r"(a) : "l"(p));
    return a;
}

#define MMA_BF16(c, a, b0, b1)                                                   \
    asm volatile("mma.sync.aligned.m16n8k16.row.col.f32.bf16.bf16.f32 "          \
        "{%0,%1,%2,%3}, {%4,%5,%6,%7}, {%8,%9}, {%0,%1,%2,%3};"                  \
        : "+f"((c)[0]), "+f"((c)[1]), "+f"((c)[2]), "+f"((c)[3])                 \
        : "r"((a)[0]), "r"((a)[1]), "r"((a)[2]), "r"((a)[3]), "r"(b0), "r"(b1))

#define LDSM_X4(r, addr)                                                         \
    asm volatile("ldmatrix.sync.aligned.m8n8.x4.shared.b16 {%0,%1,%2,%3}, [%4];" \
        : "=r"((r)[0]), "=r"((r)[1]), "=r"((r)[2]), "=r"((r)[3]) : "r"(addr))

// --------------------------- CSR construction ------------------------------
__global__ void k_init(int n) {
    int i = blockIdx.x * blockDim.x + threadIdx.x;
    if (i < n) { g_cnt[i] = 0; g_cur[i] = 0; }
}
__global__ void k_hist(const int* __restrict__ ei, int E) {
    int e = blockIdx.x * blockDim.x + threadIdx.x;
    int is64 = g_is64;
    if (e < E) atomicAdd(&g_cnt[load_idx(ei, (long long)E + e, is64)], 1);
}
__global__ void k_scanA(int n) {
    __shared__ int sh[1024];
    int t = threadIdx.x;
    int i = blockIdx.x * 1024 + t;
    sh[t] = (i < n) ? g_cnt[i] : 0;
    __syncthreads();
#pragma unroll
    for (int d = 512; d > 0; d >>= 1) {
        if (t < d) sh[t] += sh[t + d];
        __syncthreads();
    }
    if (t == 0) g_blksum[blockIdx.x] = sh[0];
}
__global__ void k_scanB(int nb) {
    __shared__ int sh[128];
    int t = threadIdx.x;
    int v = (t < nb) ? g_blksum[t] : 0;
    sh[t] = v;
    __syncthreads();
#pragma unroll
    for (int d = 1; d < 128; d <<= 1) {
        int u = 0;
        if (t >= d) u = sh[t - d];
        __syncthreads();
        if (t >= d) sh[t] += u;
        __syncthreads();
    }
    if (t < nb) g_blkoff[t] = sh[t] - v;
}
__global__ void k_scanC(int n) {
    __shared__ int sh[1024];
    int t = threadIdx.x;
    int i = blockIdx.x * 1024 + t;
    int c = (i < n) ? g_cnt[i] : 0;
    sh[t] = c;
    __syncthreads();
#pragma unroll
    for (int d = 1; d < 1024; d <<= 1) {
        int u = 0;
        if (t >= d) u = sh[t - d];
        __syncthreads();
        if (t >= d) sh[t] += u;
        __syncthreads();
    }
    if (i < n) {
        int off = g_blkoff[blockIdx.x] + sh[t] - c;
        g_off[i] = off;
        g_dis[i] = rsqrtf((float)(c + 1));
        if (i == n - 1) g_off[n] = off + c;
    }
}
__global__ void k_scatter(const int* __restrict__ ei, int E) {
    int e = blockIdx.x * blockDim.x + threadIdx.x;
    int is64 = g_is64;
    if (e < E) {
        int s = load_idx(ei, e, is64);
        int d = load_idx(ei, (long long)E + e, is64);
        int p = g_off[d] + atomicAdd(&g_cur[d], 1);
        g_esrc[p] = s;
        g_enrm[p] = g_dis[s] * g_dis[d];
    }
}

// ------------------ W1 split: fp32 [512,128] -> bf16 hi/lo W^T [128,512] ----
__global__ void k_wconv(const float* __restrict__ W1) {
    int i = blockIdx.x * blockDim.x + threadIdx.x;
    if (i < FIN * HID) {
        int k = i / HID, n = i % HID;
        float w = W1[i];
        __nv_bfloat16 h = __float2bfloat16(w);
        __nv_bfloat16 l = __float2bfloat16(w - __bfloat162float(h));
        g_w1h[(size_t)n * FIN + k] = h;
        g_w1l[(size_t)n * FIN + k] = l;
    }
}

// ---------- GEMM1 via mma.sync: [N,512] x [512,128] -> g_h1 ----------------
// CTA tile 128x128, K chunks of 32. 8 warps: warp tile 32(M) x 64(N).
// ldmatrix.x4 fragment loads (conflict-free with SA=40-half stride).
#define SA 40

__global__ __launch_bounds__(256) void k_gemm1_mma(const float* __restrict__ X, int M) {
    __shared__ __nv_bfloat16 sAh[128 * SA];
    __shared__ __nv_bfloat16 sAl[128 * SA];
    __shared__ __nv_bfloat16 sBh[128 * SA];
    __shared__ __nv_bfloat16 sBl[128 * SA];

    int t    = threadIdx.x;
    int lane = t & 31;
    int wid  = t >> 5;
    int wm   = wid & 3;   // 0..3 : M groups of 32
    int wn   = wid >> 2;  // 0..1 : N groups of 64
    int blockRow = blockIdx.x * 128;

    float acc[2][8][4];
#pragma unroll
    for (int mi = 0; mi < 2; mi++)
#pragma unroll
        for (int ni = 0; ni < 8; ni++)
#pragma unroll
            for (int c = 0; c < 4; c++) acc[mi][ni][c] = 0.f;

    uint32_t sAh_b = smem_u32(sAh), sAl_b = smem_u32(sAl);
    uint32_t sBh_b = smem_u32(sBh), sBl_b = smem_u32(sBl);

    // ldmatrix lane address components (derived from x4 group->matrix mapping)
    const int arow = (lane & 7) + ((lane & 8)  ? 8 : 0);
    const int acol = (lane & 16) ? 8 : 0;
    const int brow = (lane & 7) + ((lane & 16) ? 8 : 0);
    const int bcol = (lane & 8)  ? 8 : 0;

    for (int ch = 0; ch < 16; ch++) {
        int kt = ch * 32;
        // A fill: 128 rows x 32 k, fp32 -> bf16 hi/lo
#pragma unroll
        for (int i = 0; i < 4; i++) {
            int f  = t + i * 256;
            int r  = f >> 3;
            int c4 = f & 7;
            int gr = blockRow + r;
            if (gr >= M) gr = M - 1;
            float4 v = *(const float4*)&X[(size_t)gr * FIN + kt + c4 * 4];
            ull h = (ull)pack_hi2(v.x, v.y) | ((ull)pack_hi2(v.z, v.w) << 32);
            ull l = (ull)pack_lo2(v.x, v.y) | ((ull)pack_lo2(v.z, v.w) << 32);
            *(ull*)&sAh[r * SA + c4 * 4] = h;
            *(ull*)&sAl[r * SA + c4 * 4] = l;
        }
        // B fill: 128 n-rows x 32 k from pre-split W^T
#pragma unroll
        for (int i = 0; i < 4; i++) {
            int f  = t + i * 256;
            int n  = f >> 3;
            int c4 = f & 7;
            *(ull*)&sBh[n * SA + c4 * 4] = *(const ull*)&g_w1h[(size_t)n * FIN + kt + c4 * 4];
            *(ull*)&sBl[n * SA + c4 * 4] = *(const ull*)&g_w1l[(size_t)n * FIN + kt + c4 * 4];
        }
        __syncthreads();

#pragma unroll
        for (int kk = 0; kk < 2; kk++) {
            uint32_t ah[2][4], al[2][4];
#pragma unroll
            for (int mi = 0; mi < 2; mi++) {
                int r0 = wm * 32 + mi * 16;
                uint32_t aoff = (uint32_t)(((r0 + arow) * SA + kk * 16 + acol) << 1);
                LDSM_X4(ah[mi], sAh_b + aoff);
                LDSM_X4(al[mi], sAl_b + aoff);
            }
#pragma unroll
            for (int j = 0; j < 4; j++) {
                int n0 = wn * 64 + j * 16;
                uint32_t boff = (uint32_t)(((n0 + brow) * SA + kk * 16 + bcol) << 1);
                uint32_t bh[4], bl[4];
                LDSM_X4(bh, sBh_b + boff);
                LDSM_X4(bl, sBl_b + boff);
#pragma unroll
                for (int s = 0; s < 2; s++) {
                    int ni = 2 * j + s;
#pragma unroll
                    for (int mi = 0; mi < 2; mi++) {
                        MMA_BF16(acc[mi][ni], ah[mi], bh[2 * s], bh[2 * s + 1]);
                        MMA_BF16(acc[mi][ni], ah[mi], bl[2 * s], bl[2 * s + 1]);
                        MMA_BF16(acc[mi][ni], al[mi], bh[2 * s], bh[2 * s + 1]);
                    }
                }
            }
        }
        __syncthreads();
    }

#pragma unroll
    for (int mi = 0; mi < 2; mi++) {
        int r0 = blockRow + wm * 32 + mi * 16 + (lane >> 2);
#pragma unroll
        for (int ni = 0; ni < 8; ni++) {
            int c = wn * 64 + ni * 8 + (lane & 3) * 2;
            if (r0 < M)
                *(float2*)&g_h1[(size_t)r0 * HID + c] = make_float2(acc[mi][ni][0], acc[mi][ni][1]);
            if (r0 + 8 < M)
                *(float2*)&g_h1[(size_t)(r0 + 8) * HID + c] = make_float2(acc[mi][ni][2], acc[mi][ni][3]);
        }
    }
}

// ------------------ Aggregation 1: warp per node, 128 feats ----------------
__global__ void k_agg1(const float* __restrict__ b1, int n) {
    int w = (blockIdx.x * blockDim.x + threadIdx.x) >> 5;
    if (w >= n) return;
    int l = threadIdx.x & 31;

    float di = g_dis[w];
    float dself = di * di;

    float4 acc = *(const float4*)&g_h1[(size_t)w * HID + l * 4];
    acc.x *= dself; acc.y *= dself; acc.z *= dself; acc.w *= dself;

    int beg = g_off[w], end = g_off[w + 1];
    for (int p = beg; p < end; p++) {
        int   s  = g_esrc[p];
        float wt = g_enrm[p];
        float4 v = *(const float4*)&g_h1[(size_t)s * HID + l * 4];
        acc.x = fmaf(v.x, wt, acc.x);
        acc.y = fmaf(v.y, wt, acc.y);
        acc.z = fmaf(v.z, wt, acc.z);
        acc.w = fmaf(v.w, wt, acc.w);
    }
    float4 bb = *(const float4*)&b1[l * 4];
    acc.x = fmaxf(acc.x + bb.x, 0.f);
    acc.y = fmaxf(acc.y + bb.y, 0.f);
    acc.z = fmaxf(acc.z + bb.z, 0.f);
    acc.w = fmaxf(acc.w + bb.w, 0.f);
    *(float4*)&g_a1[(size_t)w * HID + l * 4] = acc;
}

// --------------------- GEMM2: [N,128] @ [128,40] -> g_h2 -------------------
__global__ __launch_bounds__(256, 2) void k_gemm2(const float* __restrict__ W2, int M) {
    __shared__ float As[16][260];
    __shared__ float Ws[16][NCLS];

    int t  = threadIdx.x;
    int tx = t & 7;
    int ty = t >> 3;
    int blockRow = blockIdx.x * 256;

    float acc[8][5];
#pragma unroll
    for (int i = 0; i < 8; i++)
#pragma unroll
        for (int j = 0; j < 5; j++) acc[i][j] = 0.f;

    for (int kt = 0; kt < HID; kt += 16) {
#pragma unroll
        for (int i = 0; i < 4; i++) {
            int slot = t + i * 256;
            int r  = slot >> 2;
            int c4 = slot & 3;
            int gr = blockRow + r;
            if (gr >= M) gr = M - 1;
            float4 v = *(const float4*)&g_a1[(size_t)gr * HID + kt + c4 * 4];
            As[c4 * 4 + 0][r] = v.x;
            As[c4 * 4 + 1][r] = v.y;
            As[c4 * 4 + 2][r] = v.z;
            As[c4 * 4 + 3][r] = v.w;
        }
        if (t < 160) {
            int r  = t / 10;
            int c4 = t % 10;
            float4 v = *(const float4*)&W2[(size_t)(kt + r) * NCLS + c4 * 4];
            *(float4*)&Ws[r][c4 * 4] = v;
        }
        __syncthreads();

#pragma unroll
        for (int k = 0; k < 16; k++) {
            float a[8], wv[5];
#pragma unroll
            for (int i = 0; i < 8; i++) a[i] = As[k][ty * 8 + i];
#pragma unroll
            for (int j = 0; j < 5; j++) wv[j] = Ws[k][tx * 5 + j];
#pragma unroll
            for (int i = 0; i < 8; i++)
#pragma unroll
                for (int j = 0; j < 5; j++) acc[i][j] = fmaf(a[i], wv[j], acc[i][j]);
        }
        __syncthreads();
    }

#pragma unroll
    for (int i = 0; i < 8; i++) {
        int gr = blockRow + ty * 8 + i;
        if (gr < M) {
#pragma unroll
            for (int j = 0; j < 5; j++)
                g_h2[(size_t)gr * NCLS + tx * 5 + j] = acc[i][j];
        }
    }
}

// ------- Aggregation 2 + bias + log_softmax: warp per node, 40 feats -------
__global__ void k_agg2(const float* __restrict__ b2, float* __restrict__ out, int n) {
    int w = (blockIdx.x * blockDim.x + threadIdx.x) >> 5;
    if (w >= n) return;
    int l = threadIdx.x & 31;
    bool has2 = (l < 8);

    float di = g_dis[w];
    float dself = di * di;

    const float* row = &g_h2[(size_t)w * NCLS];
    float acc0 = row[l] * dself;
    float acc1 = has2 ? row[32 + l] * dself : 0.f;

    int beg = g_off[w], end = g_off[w + 1];
    for (int p = beg; p < end; p++) {
        int   s  = g_esrc[p];
        float wt = g_enrm[p];
        const float* r2 = &g_h2[(size_t)s * NCLS];
        acc0 = fmaf(r2[l], wt, acc0);
        if (has2) acc1 = fmaf(r2[32 + l], wt, acc1);
    }
    acc0 += b2[l];
    if (has2) acc1 += b2[32 + l];

    float m = has2 ? fmaxf(acc0, acc1) : acc0;
#pragma unroll
    for (int o = 16; o >= 1; o >>= 1) m = fmaxf(m, __shfl_xor_sync(0xffffffffu, m, o));
    float e = expf(acc0 - m) + (has2 ? expf(acc1 - m) : 0.f);
#pragma unroll
    for (int o = 16; o >= 1; o >>= 1) e += __shfl_xor_sync(0xffffffffu, e, o);
    float lse = m + logf(e);

    out[(size_t)w * NCLS + l] = acc0 - lse;
    if (has2) out[(size_t)w * NCLS + 32 + l] = acc1 - lse;
}

// --------------------------------- launch ----------------------------------
// Order chosen so k_gemm1_mma is launch #6 (ncu captures with -s 5 -c 1).
// Dependencies: wconv->gemm1; probe->hist/scatter; hist->scanA->scanB->scanC
// ->scatter; gemm1+scatter->agg1->gemm2->agg2. All hold in this order.
extern "C" void kernel_launch(void* const* d_in, const int* in_sizes, int n_in,
                              void* d_out, int out_size) {
    const float* x  = (const float*)d_in[0];
    const int*   ei = (const int*)d_in[1];
    const float* W1 = (const float*)d_in[2];
    const float* b1 = (const float*)d_in[3];
    const float* W2 = (const float*)d_in[4];
    const float* b2 = (const float*)d_in[5];
    float*       out = (float*)d_out;

    int N = in_sizes[0] / FIN;       // 100000
    int E = in_sizes[1] / 2;         // 1600000
    int nb = (N + 1023) / 1024;

    k_wconv<<<(FIN * HID + 255) / 256, 256>>>(W1);          // 1
    k_probe<<<1, 1>>>((const unsigned*)d_in[1]);            // 2
    k_init<<<(N + 255) / 256, 256>>>(N);                    // 3
    k_hist<<<(E + 255) / 256, 256>>>(ei, E);                // 4
    k_scanA<<<nb, 1024>>>(N);                               // 5
    k_gemm1_mma<<<(N + 127) / 128, 256>>>(x, N);            // 6  <- profiled
    k_scanB<<<1, 128>>>(nb);                                // 7
    k_scanC<<<nb, 1024>>>(N);                               // 8
    k_scatter<<<(E + 255) / 256, 256>>>(ei, E);             // 9
    k_agg1<<<(N * 32 + 255) / 256, 256>>>(b1, N);           // 10
    k_gemm2<<<(N + 255) / 256, 256>>>(W2, N);               // 11
    k_agg2<<<(N * 32 + 255) / 256, 256>>>(b2, out, N);      // 12
}

// round 9
// speedup vs baseline: 1.2044x; 1.2044x over previous
#include <cuda_runtime.h>
#include <cuda_bf16.h>
#include <math.h>
#include <stdint.h>

// ---------------------------------------------------------------------------
// GCN 2-layer forward. R9: revert GEMM1 to R7 scalar-LDS HMMA (ldmatrix
// variant regressed 352->422); order launches so gemm1 is #4 (the slot the
// profiler empirically captures).
// ---------------------------------------------------------------------------

#define NMAX 100000
#define EMAX 1600000
#define FIN  512
#define HID  128
#define NCLS 40
#define NBLK ((NMAX + 1023) / 1024)

typedef unsigned long long ull;

// --------------------------- device scratch --------------------------------
__device__ int   g_is64;
__device__ int   g_cnt[NMAX];
__device__ int   g_off[NMAX + 1];
__device__ int   g_cur[NMAX];
__device__ float g_dis[NMAX];
__device__ int   g_blksum[NBLK];
__device__ int   g_blkoff[NBLK];
__device__ int   g_esrc[EMAX];
__device__ float g_enrm[EMAX];
__device__ __align__(128) __nv_bfloat16 g_w1h[(size_t)HID * FIN];  // W1^T hi
__device__ __align__(128) __nv_bfloat16 g_w1l[(size_t)HID * FIN];  // W1^T lo
__device__ __align__(128) float g_h1[(size_t)NMAX * HID];
__device__ __align__(128) float g_a1[(size_t)NMAX * HID];
__device__ __align__(128) float g_h2[(size_t)NMAX * NCLS];

// --------------------------- helpers ---------------------------------------
__device__ __forceinline__ int load_idx(const int* __restrict__ p, long long slot, int is64) {
    return is64 ? p[2 * slot] : p[slot];
}
__global__ void k_probe(const unsigned* __restrict__ p) {
    unsigned nz = 0;
    for (int i = 1; i < 256; i += 2) nz |= p[i];
    g_is64 = (nz == 0u) ? 1 : 0;
}

__device__ __forceinline__ unsigned pack_hi2(float x, float y) {
    __nv_bfloat16 hx = __float2bfloat16(x), hy = __float2bfloat16(y);
    return (unsigned)__bfloat16_as_ushort(hx) | ((unsigned)__bfloat16_as_ushort(hy) << 16);
}
__device__ __forceinline__ unsigned pack_lo2(float x, float y) {
    __nv_bfloat16 hx = __float2bfloat16(x), hy = __float2bfloat16(y);
    __nv_bfloat16 lx = __float2bfloat16(x - __bfloat162float(hx));
    __nv_bfloat16 ly = __float2bfloat16(y - __bfloat162float(hy));
    return (unsigned)__bfloat16_as_ushort(lx) | ((unsigned)__bfloat16_as_ushort(ly) << 16);
}

#define MMA_BF16(c, a, b0, b1)                                                   \
    asm volatile("mma.sync.aligned.m16n8k16.row.col.f32.bf16.bf16.f32 "          \
        "{%0,%1,%2,%3}, {%4,%5,%6,%7}, {%8,%9}, {%0,%1,%2,%3};"                  \
        : "+f"((c)[0]), "+f"((c)[1]), "+f"((c)[2]), "+f"((c)[3])                 \
        : "r"((a)[0]), "r"((a)[1]), "r"((a)[2]), "r"((a)[3]), "r"(b0), "r"(b1))

// --------------------------- CSR construction ------------------------------
__global__ void k_init(int n) {
    int i = blockIdx.x * blockDim.x + threadIdx.x;
    if (i < n) { g_cnt[i] = 0; g_cur[i] = 0; }
}
__global__ void k_hist(const int* __restrict__ ei, int E) {
    int e = blockIdx.x * blockDim.x + threadIdx.x;
    int is64 = g_is64;
    if (e < E) atomicAdd(&g_cnt[load_idx(ei, (long long)E + e, is64)], 1);
}
__global__ void k_scanA(int n) {
    __shared__ int sh[1024];
    int t = threadIdx.x;
    int i = blockIdx.x * 1024 + t;
    sh[t] = (i < n) ? g_cnt[i] : 0;
    __syncthreads();
#pragma unroll
    for (int d = 512; d > 0; d >>= 1) {
        if (t < d) sh[t] += sh[t + d];
        __syncthreads();
    }
    if (t == 0) g_blksum[blockIdx.x] = sh[0];
}
__global__ void k_scanB(int nb) {
    __shared__ int sh[128];
    int t = threadIdx.x;
    int v = (t < nb) ? g_blksum[t] : 0;
    sh[t] = v;
    __syncthreads();
#pragma unroll
    for (int d = 1; d < 128; d <<= 1) {
        int u = 0;
        if (t >= d) u = sh[t - d];
        __syncthreads();
        if (t >= d) sh[t] += u;
        __syncthreads();
    }
    if (t < nb) g_blkoff[t] = sh[t] - v;
}
__global__ void k_scanC(int n) {
    __shared__ int sh[1024];
    int t = threadIdx.x;
    int i = blockIdx.x * 1024 + t;
    int c = (i < n) ? g_cnt[i] : 0;
    sh[t] = c;
    __syncthreads();
#pragma unroll
    for (int d = 1; d < 1024; d <<= 1) {
        int u = 0;
        if (t >= d) u = sh[t - d];
        __syncthreads();
        if (t >= d) sh[t] += u;
        __syncthreads();
    }
    if (i < n) {
        int off = g_blkoff[blockIdx.x] + sh[t] - c;
        g_off[i] = off;
        g_dis[i] = rsqrtf((float)(c + 1));
        if (i == n - 1) g_off[n] = off + c;
    }
}
__global__ void k_scatter(const int* __restrict__ ei, int E) {
    int e = blockIdx.x * blockDim.x + threadIdx.x;
    int is64 = g_is64;
    if (e < E) {
        int s = load_idx(ei, e, is64);
        int d = load_idx(ei, (long long)E + e, is64);
        int p = g_off[d] + atomicAdd(&g_cur[d], 1);
        g_esrc[p] = s;
        g_enrm[p] = g_dis[s] * g_dis[d];
    }
}

// ------------------ W1 split: fp32 [512,128] -> bf16 hi/lo W^T [128,512] ----
__global__ void k_wconv(const float* __restrict__ W1) {
    int i = blockIdx.x * blockDim.x + threadIdx.x;
    if (i < FIN * HID) {
        int k = i / HID, n = i % HID;
        float w = W1[i];
        __nv_bfloat16 h = __float2bfloat16(w);
        __nv_bfloat16 l = __float2bfloat16(w - __bfloat162float(h));
        g_w1h[(size_t)n * FIN + k] = h;
        g_w1l[(size_t)n * FIN + k] = l;
    }
}

// ---------- GEMM1 via mma.sync: [N,512] x [512,128] -> g_h1 ----------------
// CTA tile 128x128, K chunks of 32. 8 warps: warp tile 32(M) x 64(N).
// Scalar LDS fragment loads (R7 layout; ldmatrix variant was slower).
#define SA 40   // smem stride in halves (conflict-free fragment reads)

__global__ __launch_bounds__(256) void k_gemm1_mma(const float* __restrict__ X, int M) {
    __shared__ __nv_bfloat16 sAh[128 * SA];
    __shared__ __nv_bfloat16 sAl[128 * SA];
    __shared__ __nv_bfloat16 sBh[128 * SA];
    __shared__ __nv_bfloat16 sBl[128 * SA];

    int t    = threadIdx.x;
    int lane = t & 31;
    int wid  = t >> 5;
    int wm   = wid & 3;   // 0..3 : M groups of 32
    int wn   = wid >> 2;  // 0..1 : N groups of 64
    int blockRow = blockIdx.x * 128;

    float acc[2][8][4];
#pragma unroll
    for (int mi = 0; mi < 2; mi++)
#pragma unroll
        for (int ni = 0; ni < 8; ni++)
#pragma unroll
            for (int c = 0; c < 4; c++) acc[mi][ni][c] = 0.f;

    const int lg = lane >> 2;          // 0..7
    const int lk = (lane & 3) * 2;     // 0,2,4,6

    for (int ch = 0; ch < 16; ch++) {
        int kt = ch * 32;
        // A fill: 128 rows x 32 k, fp32 -> bf16 hi/lo
#pragma unroll
        for (int i = 0; i < 4; i++) {
            int f  = t + i * 256;        // 0..1023
            int r  = f >> 3;             // 0..127
            int c4 = f & 7;              // 0..7 -> k offset c4*4
            int gr = blockRow + r;
            if (gr >= M) gr = M - 1;
            float4 v = *(const float4*)&X[(size_t)gr * FIN + kt + c4 * 4];
            ull h = (ull)pack_hi2(v.x, v.y) | ((ull)pack_hi2(v.z, v.w) << 32);
            ull l = (ull)pack_lo2(v.x, v.y) | ((ull)pack_lo2(v.z, v.w) << 32);
            *(ull*)&sAh[r * SA + c4 * 4] = h;
            *(ull*)&sAl[r * SA + c4 * 4] = l;
        }
        // B fill: 128 n-rows x 32 k from pre-split W^T
#pragma unroll
        for (int i = 0; i < 4; i++) {
            int f  = t + i * 256;
            int n  = f >> 3;
            int c4 = f & 7;
            *(ull*)&sBh[n * SA + c4 * 4] = *(const ull*)&g_w1h[(size_t)n * FIN + kt + c4 * 4];
            *(ull*)&sBl[n * SA + c4 * 4] = *(const ull*)&g_w1l[(size_t)n * FIN + kt + c4 * 4];
        }
        __syncthreads();

#pragma unroll
        for (int kk = 0; kk < 2; kk++) {
            int k0 = kk * 16 + lk;
            uint32_t ah[2][4], al[2][4];
#pragma unroll
            for (int mi = 0; mi < 2; mi++) {
                int r0 = wm * 32 + mi * 16 + lg;
                ah[mi][0] = *(const uint32_t*)&sAh[r0 * SA + k0];
                ah[mi][1] = *(const uint32_t*)&sAh[(r0 + 8) * SA + k0];
                ah[mi][2] = *(const uint32_t*)&sAh[r0 * SA + k0 + 8];
                ah[mi][3] = *(const uint32_t*)&sAh[(r0 + 8) * SA + k0 + 8];
                al[mi][0] = *(const uint32_t*)&sAl[r0 * SA + k0];
                al[mi][1] = *(const uint32_t*)&sAl[(r0 + 8) * SA + k0];
                al[mi][2] = *(const uint32_t*)&sAl[r0 * SA + k0 + 8];
                al[mi][3] = *(const uint32_t*)&sAl[(r0 + 8) * SA + k0 + 8];
            }
#pragma unroll
            for (int ni = 0; ni < 8; ni++) {
                int c0 = wn * 64 + ni * 8 + lg;
                uint32_t bh0 = *(const uint32_t*)&sBh[c0 * SA + k0];
                uint32_t bh1 = *(const uint32_t*)&sBh[c0 * SA + k0 + 8];
                uint32_t bl0 = *(const uint32_t*)&sBl[c0 * SA + k0];
                uint32_t bl1 = *(const uint32_t*)&sBl[c0 * SA + k0 + 8];
#pragma unroll
                for (int mi = 0; mi < 2; mi++) {
                    MMA_BF16(acc[mi][ni], ah[mi], bh0, bh1);
                    MMA_BF16(acc[mi][ni], ah[mi], bl0, bl1);
                    MMA_BF16(acc[mi][ni], al[mi], bh0, bh1);
                }
            }
        }
        __syncthreads();
    }

#pragma unroll
    for (int mi = 0; mi < 2; mi++) {
        int r0 = blockRow + wm * 32 + mi * 16 + (lane >> 2);
#pragma unroll
        for (int ni = 0; ni < 8; ni++) {
            int c = wn * 64 + ni * 8 + (lane & 3) * 2;
            if (r0 < M)
                *(float2*)&g_h1[(size_t)r0 * HID + c] = make_float2(acc[mi][ni][0], acc[mi][ni][1]);
            if (r0 + 8 < M)
                *(float2*)&g_h1[(size_t)(r0 + 8) * HID + c] = make_float2(acc[mi][ni][2], acc[mi][ni][3]);
        }
    }
}

// ------------------ Aggregation 1: warp per node, 128 feats ----------------
__global__ void k_agg1(const float* __restrict__ b1, int n) {
    int w = (blockIdx.x * blockDim.x + threadIdx.x) >> 5;
    if (w >= n) return;
    int l = threadIdx.x & 31;

    float di = g_dis[w];
    float dself = di * di;

    float4 acc = *(const float4*)&g_h1[(size_t)w * HID + l * 4];
    acc.x *= dself; acc.y *= dself; acc.z *= dself; acc.w *= dself;

    int beg = g_off[w], end = g_off[w + 1];
    for (int p = beg; p < end; p++) {
        int   s  = g_esrc[p];
        float wt = g_enrm[p];
        float4 v = *(const float4*)&g_h1[(size_t)s * HID + l * 4];
        acc.x = fmaf(v.x, wt, acc.x);
        acc.y = fmaf(v.y, wt, acc.y);
        acc.z = fmaf(v.z, wt, acc.z);
        acc.w = fmaf(v.w, wt, acc.w);
    }
    float4 bb = *(const float4*)&b1[l * 4];
    acc.x = fmaxf(acc.x + bb.x, 0.f);
    acc.y = fmaxf(acc.y + bb.y, 0.f);
    acc.z = fmaxf(acc.z + bb.z, 0.f);
    acc.w = fmaxf(acc.w + bb.w, 0.f);
    *(float4*)&g_a1[(size_t)w * HID + l * 4] = acc;
}

// --------------------- GEMM2: [N,128] @ [128,40] -> g_h2 -------------------
__global__ __launch_bounds__(256, 2) void k_gemm2(const float* __restrict__ W2, int M) {
    __shared__ float As[16][260];
    __shared__ float Ws[16][NCLS];

    int t  = threadIdx.x;
    int tx = t & 7;
    int ty = t >> 3;
    int blockRow = blockIdx.x * 256;

    float acc[8][5];
#pragma unroll
    for (int i = 0; i < 8; i++)
#pragma unroll
        for (int j = 0; j < 5; j++) acc[i][j] = 0.f;

    for (int kt = 0; kt < HID; kt += 16) {
#pragma unroll
        for (int i = 0; i < 4; i++) {
            int slot = t + i * 256;
            int r  = slot >> 2;
            int c4 = slot & 3;
            int gr = blockRow + r;
            if (gr >= M) gr = M - 1;
            float4 v = *(const float4*)&g_a1[(size_t)gr * HID + kt + c4 * 4];
            As[c4 * 4 + 0][r] = v.x;
            As[c4 * 4 + 1][r] = v.y;
            As[c4 * 4 + 2][r] = v.z;
            As[c4 * 4 + 3][r] = v.w;
        }
        if (t < 160) {
            int r  = t / 10;
            int c4 = t % 10;
            float4 v = *(const float4*)&W2[(size_t)(kt + r) * NCLS + c4 * 4];
            *(float4*)&Ws[r][c4 * 4] = v;
        }
        __syncthreads();

#pragma unroll
        for (int k = 0; k < 16; k++) {
            float a[8], wv[5];
#pragma unroll
            for (int i = 0; i < 8; i++) a[i] = As[k][ty * 8 + i];
#pragma unroll
            for (int j = 0; j < 5; j++) wv[j] = Ws[k][tx * 5 + j];
#pragma unroll
            for (int i = 0; i < 8; i++)
#pragma unroll
                for (int j = 0; j < 5; j++) acc[i][j] = fmaf(a[i], wv[j], acc[i][j]);
        }
        __syncthreads();
    }

#pragma unroll
    for (int i = 0; i < 8; i++) {
        int gr = blockRow + ty * 8 + i;
        if (gr < M) {
#pragma unroll
            for (int j = 0; j < 5; j++)
                g_h2[(size_t)gr * NCLS + tx * 5 + j] = acc[i][j];
        }
    }
}

// ------- Aggregation 2 + bias + log_softmax: warp per node, 40 feats -------
__global__ void k_agg2(const float* __restrict__ b2, float* __restrict__ out, int n) {
    int w = (blockIdx.x * blockDim.x + threadIdx.x) >> 5;
    if (w >= n) return;
    int l = threadIdx.x & 31;
    bool has2 = (l < 8);

    float di = g_dis[w];
    float dself = di * di;

    const float* row = &g_h2[(size_t)w * NCLS];
    float acc0 = row[l] * dself;
    float acc1 = has2 ? row[32 + l] * dself : 0.f;

    int beg = g_off[w], end = g_off[w + 1];
    for (int p = beg; p < end; p++) {
        int   s  = g_esrc[p];
        float wt = g_enrm[p];
        const float* r2 = &g_h2[(size_t)s * NCLS];
        acc0 = fmaf(r2[l], wt, acc0);
        if (has2) acc1 = fmaf(r2[32 + l], wt, acc1);
    }
    acc0 += b2[l];
    if (has2) acc1 += b2[32 + l];

    float m = has2 ? fmaxf(acc0, acc1) : acc0;
#pragma unroll
    for (int o = 16; o >= 1; o >>= 1) m = fmaxf(m, __shfl_xor_sync(0xffffffffu, m, o));
    float e = expf(acc0 - m) + (has2 ? expf(acc1 - m) : 0.f);
#pragma unroll
    for (int o = 16; o >= 1; o >>= 1) e += __shfl_xor_sync(0xffffffffu, e, o);
    float lse = m + logf(e);

    out[(size_t)w * NCLS + l] = acc0 - lse;
    if (has2) out[(size_t)w * NCLS + 32 + l] = acc1 - lse;
}

// --------------------------------- launch ----------------------------------
// gemm1 placed as our 4th launch: the profiler empirically captures launch #4
// of this sequence (R4/R5/R7/R8 all profiled whatever kernel sat there).
// Deps: wconv->gemm1; probe->hist/scatter; init->hist; hist->scanA->scanB->
// scanC->scatter; gemm1+scatter->agg1->gemm2->agg2. All satisfied.
extern "C" void kernel_launch(void* const* d_in, const int* in_sizes, int n_in,
                              void* d_out, int out_size) {
    const float* x  = (const float*)d_in[0];
    const int*   ei = (const int*)d_in[1];
    const float* W1 = (const float*)d_in[2];
    const float* b1 = (const float*)d_in[3];
    const float* W2 = (const float*)d_in[4];
    const float* b2 = (const float*)d_in[5];
    float*       out = (float*)d_out;

    int N = in_sizes[0] / FIN;       // 100000
    int E = in_sizes[1] / 2;         // 1600000
    int nb = (N + 1023) / 1024;

    k_wconv<<<(FIN * HID + 255) / 256, 256>>>(W1);          // 1
    k_probe<<<1, 1>>>((const unsigned*)d_in[1]);            // 2
    k_init<<<(N + 255) / 256, 256>>>(N);                    // 3
    k_gemm1_mma<<<(N + 127) / 128, 256>>>(x, N);            // 4  <- profiled
    k_hist<<<(E + 255) / 256, 256>>>(ei, E);                // 5
    k_scanA<<<nb, 1024>>>(N);                               // 6
    k_scanB<<<1, 128>>>(nb);                                // 7
    k_scanC<<<nb, 1024>>>(N);                               // 8
    k_scatter<<<(E + 255) / 256, 256>>>(ei, E);             // 9
    k_agg1<<<(N * 32 + 255) / 256, 256>>>(b1, N);           // 10
    k_gemm2<<<(N + 255) / 256, 256>>>(W2, N);               // 11
    k_agg2<<<(N * 32 + 255) / 256, 256>>>(b2, out, N);      // 12
}

// round 12
// speedup vs baseline: 1.3375x; 1.1105x over previous
#include <cuda_runtime.h>
#include <cuda_bf16.h>
#include <cuda_fp16.h>
#include <math.h>
#include <stdint.h>

// ---------------------------------------------------------------------------
// GCN 2-layer forward. R12: R10 design (fp16 2-term GEMM1 + fp16 h1 gather)
// with the __ushort2half2 compile error fixed (bit-reinterpret instead).
// ---------------------------------------------------------------------------

#define NMAX 100000
#define EMAX 1600000
#define FIN  512
#define HID  128
#define NCLS 40
#define NBLK ((NMAX + 1023) / 1024)

typedef unsigned long long ull;

// --------------------------- device scratch --------------------------------
__device__ int   g_is64;
__device__ int   g_cnt[NMAX];
__device__ int   g_off[NMAX + 1];
__device__ int   g_cur[NMAX];
__device__ float g_dis[NMAX];
__device__ int   g_blksum[NBLK];
__device__ int   g_blkoff[NBLK];
__device__ int   g_esrc[EMAX];
__device__ float g_enrm[EMAX];
__device__ __align__(128) __half g_w1h[(size_t)HID * FIN];   // W1^T hi (fp16)
__device__ __align__(128) __half g_w1l[(size_t)HID * FIN];   // W1^T lo (fp16)
__device__ __align__(128) __half2 g_h1f[(size_t)NMAX * (HID / 2)];  // x@W1, fp16
__device__ __align__(128) float g_a1[(size_t)NMAX * HID];
__device__ __align__(128) float g_h2[(size_t)NMAX * NCLS];

// --------------------------- helpers ---------------------------------------
__device__ __forceinline__ int load_idx(const int* __restrict__ p, long long slot, int is64) {
    return is64 ? p[2 * slot] : p[slot];
}
__global__ void k_probe(const unsigned* __restrict__ p) {
    unsigned nz = 0;
    for (int i = 1; i < 256; i += 2) nz |= p[i];
    g_is64 = (nz == 0u) ? 1 : 0;
}

// pack 2 floats -> 2 fp16 (hi parts) in one u32
__device__ __forceinline__ unsigned pack_h2(float x, float y) {
    __half hx = __float2half_rn(x), hy = __float2half_rn(y);
    return (unsigned)__half_as_ushort(hx) | ((unsigned)__half_as_ushort(hy) << 16);
}
// reinterpret u32 as __half2 and widen to float2
__device__ __forceinline__ float2 u32_as_f2h(unsigned u) {
    __half2 h = *reinterpret_cast<__half2*>(&u);
    return __half22float2(h);
}

#define MMA_F16(c, a, b0, b1)                                                    \
    asm volatile("mma.sync.aligned.m16n8k16.row.col.f32.f16.f16.f32 "            \
        "{%0,%1,%2,%3}, {%4,%5,%6,%7}, {%8,%9}, {%0,%1,%2,%3};"                  \
        : "+f"((c)[0]), "+f"((c)[1]), "+f"((c)[2]), "+f"((c)[3])                 \
        : "r"((a)[0]), "r"((a)[1]), "r"((a)[2]), "r"((a)[3]), "r"(b0), "r"(b1))

// --------------------------- CSR construction ------------------------------
__global__ void k_init(int n) {
    int i = blockIdx.x * blockDim.x + threadIdx.x;
    if (i < n) { g_cnt[i] = 0; g_cur[i] = 0; }
}
__global__ void k_hist(const int* __restrict__ ei, int E) {
    int e = blockIdx.x * blockDim.x + threadIdx.x;
    int is64 = g_is64;
    if (e < E) atomicAdd(&g_cnt[load_idx(ei, (long long)E + e, is64)], 1);
}
__global__ void k_scanA(int n) {
    __shared__ int sh[1024];
    int t = threadIdx.x;
    int i = blockIdx.x * 1024 + t;
    sh[t] = (i < n) ? g_cnt[i] : 0;
    __syncthreads();
#pragma unroll
    for (int d = 512; d > 0; d >>= 1) {
        if (t < d) sh[t] += sh[t + d];
        __syncthreads();
    }
    if (t == 0) g_blksum[blockIdx.x] = sh[0];
}
__global__ void k_scanB(int nb) {
    __shared__ int sh[128];
    int t = threadIdx.x;
    int v = (t < nb) ? g_blksum[t] : 0;
    sh[t] = v;
    __syncthreads();
#pragma unroll
    for (int d = 1; d < 128; d <<= 1) {
        int u = 0;
        if (t >= d) u = sh[t - d];
        __syncthreads();
        if (t >= d) sh[t] += u;
        __syncthreads();
    }
    if (t < nb) g_blkoff[t] = sh[t] - v;
}
__global__ void k_scanC(int n) {
    __shared__ int sh[1024];
    int t = threadIdx.x;
    int i = blockIdx.x * 1024 + t;
    int c = (i < n) ? g_cnt[i] : 0;
    sh[t] = c;
    __syncthreads();
#pragma unroll
    for (int d = 1; d < 1024; d <<= 1) {
        int u = 0;
        if (t >= d) u = sh[t - d];
        __syncthreads();
        if (t >= d) sh[t] += u;
        __syncthreads();
    }
    if (i < n) {
        int off = g_blkoff[blockIdx.x] + sh[t] - c;
        g_off[i] = off;
        g_dis[i] = rsqrtf((float)(c + 1));
        if (i == n - 1) g_off[n] = off + c;
    }
}
__global__ void k_scatter(const int* __restrict__ ei, int E) {
    int e = blockIdx.x * blockDim.x + threadIdx.x;
    int is64 = g_is64;
    if (e < E) {
        int s = load_idx(ei, e, is64);
        int d = load_idx(ei, (long long)E + e, is64);
        int p = g_off[d] + atomicAdd(&g_cur[d], 1);
        g_esrc[p] = s;
        g_enrm[p] = g_dis[s] * g_dis[d];
    }
}

// ------------------ W1 split: fp32 [512,128] -> fp16 hi/lo W^T [128,512] ----
__global__ void k_wconv(const float* __restrict__ W1) {
    int i = blockIdx.x * blockDim.x + threadIdx.x;
    if (i < FIN * HID) {
        int k = i / HID, n = i % HID;
        float w = W1[i];
        __half h = __float2half_rn(w);
        __half l = __float2half_rn(w - __half2float(h));
        g_w1h[(size_t)n * FIN + k] = h;
        g_w1l[(size_t)n * FIN + k] = l;
    }
}

// ---------- GEMM1 via mma.sync fp16: [N,512] x [512,128] -> g_h1f ----------
// CTA tile 128x128, K chunks of 32. 8 warps: warp tile 32(M) x 64(N).
// 2 terms: ah*bh + ah*bl (B pre-split fp16; A hi only). 64 MMA/warp/chunk.
#define SA 40   // smem stride in halves (conflict-free fragment reads)

__global__ __launch_bounds__(256) void k_gemm1_mma(const float* __restrict__ X, int M) {
    __shared__ __half sA [128 * SA];
    __shared__ __half sBh[128 * SA];
    __shared__ __half sBl[128 * SA];

    int t    = threadIdx.x;
    int lane = t & 31;
    int wid  = t >> 5;
    int wm   = wid & 3;   // 0..3 : M groups of 32
    int wn   = wid >> 2;  // 0..1 : N groups of 64
    int blockRow = blockIdx.x * 128;

    float acc[2][8][4];
#pragma unroll
    for (int mi = 0; mi < 2; mi++)
#pragma unroll
        for (int ni = 0; ni < 8; ni++)
#pragma unroll
            for (int c = 0; c < 4; c++) acc[mi][ni][c] = 0.f;

    const int lg = lane >> 2;          // 0..7
    const int lk = (lane & 3) * 2;     // 0,2,4,6

    for (int ch = 0; ch < 16; ch++) {
        int kt = ch * 32;
        // A fill: 128 rows x 32 k, fp32 -> fp16 hi
#pragma unroll
        for (int i = 0; i < 4; i++) {
            int f  = t + i * 256;        // 0..1023
            int r  = f >> 3;             // 0..127
            int c4 = f & 7;              // 0..7 -> k offset c4*4
            int gr = blockRow + r;
            if (gr >= M) gr = M - 1;
            float4 v = *(const float4*)&X[(size_t)gr * FIN + kt + c4 * 4];
            ull h = (ull)pack_h2(v.x, v.y) | ((ull)pack_h2(v.z, v.w) << 32);
            *(ull*)&sA[r * SA + c4 * 4] = h;
        }
        // B fill: 128 n-rows x 32 k from pre-split W^T
#pragma unroll
        for (int i = 0; i < 4; i++) {
            int f  = t + i * 256;
            int n  = f >> 3;
            int c4 = f & 7;
            *(ull*)&sBh[n * SA + c4 * 4] = *(const ull*)&g_w1h[(size_t)n * FIN + kt + c4 * 4];
            *(ull*)&sBl[n * SA + c4 * 4] = *(const ull*)&g_w1l[(size_t)n * FIN + kt + c4 * 4];
        }
        __syncthreads();

#pragma unroll
        for (int kk = 0; kk < 2; kk++) {
            int k0 = kk * 16 + lk;
            uint32_t ah[2][4];
#pragma unroll
            for (int mi = 0; mi < 2; mi++) {
                int r0 = wm * 32 + mi * 16 + lg;
                ah[mi][0] = *(const uint32_t*)&sA[r0 * SA + k0];
                ah[mi][1] = *(const uint32_t*)&sA[(r0 + 8) * SA + k0];
                ah[mi][2] = *(const uint32_t*)&sA[r0 * SA + k0 + 8];
                ah[mi][3] = *(const uint32_t*)&sA[(r0 + 8) * SA + k0 + 8];
            }
#pragma unroll
            for (int ni = 0; ni < 8; ni++) {
                int c0 = wn * 64 + ni * 8 + lg;
                uint32_t bh0 = *(const uint32_t*)&sBh[c0 * SA + k0];
                uint32_t bh1 = *(const uint32_t*)&sBh[c0 * SA + k0 + 8];
                uint32_t bl0 = *(const uint32_t*)&sBl[c0 * SA + k0];
                uint32_t bl1 = *(const uint32_t*)&sBl[c0 * SA + k0 + 8];
#pragma unroll
                for (int mi = 0; mi < 2; mi++) {
                    MMA_F16(acc[mi][ni], ah[mi], bh0, bh1);
                    MMA_F16(acc[mi][ni], ah[mi], bl0, bl1);
                }
            }
        }
        __syncthreads();
    }

    // epilogue: adjacent col pairs -> one __half2 store
#pragma unroll
    for (int mi = 0; mi < 2; mi++) {
        int r0 = blockRow + wm * 32 + mi * 16 + (lane >> 2);
#pragma unroll
        for (int ni = 0; ni < 8; ni++) {
            int c2 = (wn * 64 + ni * 8 + (lane & 3) * 2) >> 1;   // half2 index
            if (r0 < M)
                g_h1f[(size_t)r0 * (HID / 2) + c2] = __floats2half2_rn(acc[mi][ni][0], acc[mi][ni][1]);
            if (r0 + 8 < M)
                g_h1f[(size_t)(r0 + 8) * (HID / 2) + c2] = __floats2half2_rn(acc[mi][ni][2], acc[mi][ni][3]);
        }
    }
}

// ------------- Aggregation 1: warp per node, 128 feats, fp16 gather --------
__global__ void k_agg1(const float* __restrict__ b1, int n) {
    int w = (blockIdx.x * blockDim.x + threadIdx.x) >> 5;
    if (w >= n) return;
    int l = threadIdx.x & 31;

    float di = g_dis[w];
    float dself = di * di;

    const __half2* self = &g_h1f[(size_t)w * (HID / 2) + l * 2];
    float2 s0 = __half22float2(self[0]);
    float2 s1 = __half22float2(self[1]);
    float4 acc = make_float4(s0.x * dself, s0.y * dself, s1.x * dself, s1.y * dself);

    int beg = g_off[w], end = g_off[w + 1];
    for (int p = beg; p < end; p++) {
        int   s  = g_esrc[p];
        float wt = g_enrm[p];
        uint2 v = *(const uint2*)&g_h1f[(size_t)s * (HID / 2) + l * 2];
        float2 f0 = u32_as_f2h(v.x);
        float2 f1 = u32_as_f2h(v.y);
        acc.x = fmaf(f0.x, wt, acc.x);
        acc.y = fmaf(f0.y, wt, acc.y);
        acc.z = fmaf(f1.x, wt, acc.z);
        acc.w = fmaf(f1.y, wt, acc.w);
    }
    float4 bb = *(const float4*)&b1[l * 4];
    acc.x = fmaxf(acc.x + bb.x, 0.f);
    acc.y = fmaxf(acc.y + bb.y, 0.f);
    acc.z = fmaxf(acc.z + bb.z, 0.f);
    acc.w = fmaxf(acc.w + bb.w, 0.f);
    *(float4*)&g_a1[(size_t)w * HID + l * 4] = acc;
}

// --------------------- GEMM2: [N,128] @ [128,40] -> g_h2 -------------------
__global__ __launch_bounds__(256, 2) void k_gemm2(const float* __restrict__ W2, int M) {
    __shared__ float As[16][260];
    __shared__ float Ws[16][NCLS];

    int t  = threadIdx.x;
    int tx = t & 7;
    int ty = t >> 3;
    int blockRow = blockIdx.x * 256;

    float acc[8][5];
#pragma unroll
    for (int i = 0; i < 8; i++)
#pragma unroll
        for (int j = 0; j < 5; j++) acc[i][j] = 0.f;

    for (int kt = 0; kt < HID; kt += 16) {
#pragma unroll
        for (int i = 0; i < 4; i++) {
            int slot = t + i * 256;
            int r  = slot >> 2;
            int c4 = slot & 3;
            int gr = blockRow + r;
            if (gr >= M) gr = M - 1;
            float4 v = *(const float4*)&g_a1[(size_t)gr * HID + kt + c4 * 4];
            As[c4 * 4 + 0][r] = v.x;
            As[c4 * 4 + 1][r] = v.y;
            As[c4 * 4 + 2][r] = v.z;
            As[c4 * 4 + 3][r] = v.w;
        }
        if (t < 160) {
            int r  = t / 10;
            int c4 = t % 10;
            float4 v = *(const float4*)&W2[(size_t)(kt + r) * NCLS + c4 * 4];
            *(float4*)&Ws[r][c4 * 4] = v;
        }
        __syncthreads();

#pragma unroll
        for (int k = 0; k < 16; k++) {
            float a[8], wv[5];
#pragma unroll
            for (int i = 0; i < 8; i++) a[i] = As[k][ty * 8 + i];
#pragma unroll
            for (int j = 0; j < 5; j++) wv[j] = Ws[k][tx * 5 + j];
#pragma unroll
            for (int i = 0; i < 8; i++)
#pragma unroll
                for (int j = 0; j < 5; j++) acc[i][j] = fmaf(a[i], wv[j], acc[i][j]);
        }
        __syncthreads();
    }

#pragma unroll
    for (int i = 0; i < 8; i++) {
        int gr = blockRow + ty * 8 + i;
        if (gr < M) {
#pragma unroll
            for (int j = 0; j < 5; j++)
                g_h2[(size_t)gr * NCLS + tx * 5 + j] = acc[i][j];
        }
    }
}

// ------- Aggregation 2 + bias + log_softmax: warp per node, 40 feats -------
__global__ void k_agg2(const float* __restrict__ b2, float* __restrict__ out, int n) {
    int w = (blockIdx.x * blockDim.x + threadIdx.x) >> 5;
    if (w >= n) return;
    int l = threadIdx.x & 31;
    bool has2 = (l < 8);

    float di = g_dis[w];
    float dself = di * di;

    const float* row = &g_h2[(size_t)w * NCLS];
    float acc0 = row[l] * dself;
    float acc1 = has2 ? row[32 + l] * dself : 0.f;

    int beg = g_off[w], end = g_off[w + 1];
    for (int p = beg; p < end; p++) {
        int   s  = g_esrc[p];
        float wt = g_enrm[p];
        const float* r2 = &g_h2[(size_t)s * NCLS];
        acc0 = fmaf(r2[l], wt, acc0);
        if (has2) acc1 = fmaf(r2[32 + l], wt, acc1);
    }
    acc0 += b2[l];
    if (has2) acc1 += b2[32 + l];

    float m = has2 ? fmaxf(acc0, acc1) : acc0;
#pragma unroll
    for (int o = 16; o >= 1; o >>= 1) m = fmaxf(m, __shfl_xor_sync(0xffffffffu, m, o));
    float e = expf(acc0 - m) + (has2 ? expf(acc1 - m) : 0.f);
#pragma unroll
    for (int o = 16; o >= 1; o >>= 1) e += __shfl_xor_sync(0xffffffffu, e, o);
    float lse = m + logf(e);

    out[(size_t)w * NCLS + l] = acc0 - lse;
    if (has2) out[(size_t)w * NCLS + 32 + l] = acc1 - lse;
}

// --------------------------------- launch ----------------------------------
// gemm1 stays at launch #4 (the slot the profiler captures).
extern "C" void kernel_launch(void* const* d_in, const int* in_sizes, int n_in,
                              void* d_out, int out_size) {
    const float* x  = (const float*)d_in[0];
    const int*   ei = (const int*)d_in[1];
    const float* W1 = (const float*)d_in[2];
    const float* b1 = (const float*)d_in[3];
    const float* W2 = (const float*)d_in[4];
    const float* b2 = (const float*)d_in[5];
    float*       out = (float*)d_out;

    int N = in_sizes[0] / FIN;       // 100000
    int E = in_sizes[1] / 2;         // 1600000
    int nb = (N + 1023) / 1024;

    k_wconv<<<(FIN * HID + 255) / 256, 256>>>(W1);          // 1
    k_probe<<<1, 1>>>((const unsigned*)d_in[1]);            // 2
    k_init<<<(N + 255) / 256, 256>>>(N);                    // 3
    k_gemm1_mma<<<(N + 127) / 128, 256>>>(x, N);            // 4  <- profiled
    k_hist<<<(E + 255) / 256, 256>>>(ei, E);                // 5
    k_scanA<<<nb, 1024>>>(N);                               // 6
    k_scanB<<<1, 128>>>(nb);                                // 7
    k_scanC<<<nb, 1024>>>(N);                               // 8
    k_scatter<<<(E + 255) / 256, 256>>>(ei, E);             // 9
    k_agg1<<<(N * 32 + 255) / 256, 256>>>(b1, N);           // 10
    k_gemm2<<<(N + 255) / 256, 256>>>(W2, N);               // 11
    k_agg2<<<(N * 32 + 255) / 256, 256>>>(b2, out, N);      // 12
}

// round 13
// speedup vs baseline: 1.6612x; 1.2420x over previous
#include <cuda_runtime.h>
#include <cuda_bf16.h>
#include <cuda_fp16.h>
#include <math.h>
#include <stdint.h>

// ---------------------------------------------------------------------------
// GCN 2-layer forward. R13: spend precision headroom (measured 3.6e-6 vs 1e-3
// budget): GEMM1 pure fp16 single-term; a1/h2 fp16; GEMM2 on fp16 HMMA.
// ---------------------------------------------------------------------------

#define NMAX 100000
#define EMAX 1600000
#define FIN  512
#define HID  128
#define NCLS 40
#define NBLK ((NMAX + 1023) / 1024)

typedef unsigned long long ull;

// --------------------------- device scratch --------------------------------
__device__ int   g_is64;
__device__ int   g_cnt[NMAX];
__device__ int   g_off[NMAX + 1];
__device__ int   g_cur[NMAX];
__device__ float g_dis[NMAX];
__device__ int   g_blksum[NBLK];
__device__ int   g_blkoff[NBLK];
__device__ int   g_esrc[EMAX];
__device__ float g_enrm[EMAX];
__device__ __align__(128) __half g_w1h[(size_t)HID * FIN];          // W1^T fp16
__device__ __align__(128) __half g_w2t[(size_t)NCLS * HID];         // W2^T fp16
__device__ __align__(128) __half2 g_h1f[(size_t)NMAX * (HID / 2)];  // x@W1
__device__ __align__(128) __half2 g_a1f[(size_t)NMAX * (HID / 2)];  // relu(agg)
__device__ __align__(128) __half2 g_h2f[(size_t)NMAX * (NCLS / 2)]; // a1@W2

// --------------------------- helpers ---------------------------------------
__device__ __forceinline__ int load_idx(const int* __restrict__ p, long long slot, int is64) {
    return is64 ? p[2 * slot] : p[slot];
}
__global__ void k_probe(const unsigned* __restrict__ p) {
    unsigned nz = 0;
    for (int i = 1; i < 256; i += 2) nz |= p[i];
    g_is64 = (nz == 0u) ? 1 : 0;
}
__device__ __forceinline__ unsigned pack_h2(float x, float y) {
    __half hx = __float2half_rn(x), hy = __float2half_rn(y);
    return (unsigned)__half_as_ushort(hx) | ((unsigned)__half_as_ushort(hy) << 16);
}
__device__ __forceinline__ float2 u32_as_f2h(unsigned u) {
    __half2 h = *reinterpret_cast<__half2*>(&u);
    return __half22float2(h);
}

#define MMA_F16(c, a, b0, b1)                                                    \
    asm volatile("mma.sync.aligned.m16n8k16.row.col.f32.f16.f16.f32 "            \
        "{%0,%1,%2,%3}, {%4,%5,%6,%7}, {%8,%9}, {%0,%1,%2,%3};"                  \
        : "+f"((c)[0]), "+f"((c)[1]), "+f"((c)[2]), "+f"((c)[3])                 \
        : "r"((a)[0]), "r"((a)[1]), "r"((a)[2]), "r"((a)[3]), "r"(b0), "r"(b1))

// --------------------------- CSR construction ------------------------------
__global__ void k_init(int n) {
    int i = blockIdx.x * blockDim.x + threadIdx.x;
    if (i < n) { g_cnt[i] = 0; g_cur[i] = 0; }
}
__global__ void k_hist(const int* __restrict__ ei, int E) {
    int e = blockIdx.x * blockDim.x + threadIdx.x;
    int is64 = g_is64;
    if (e < E) atomicAdd(&g_cnt[load_idx(ei, (long long)E + e, is64)], 1);
}
__global__ void k_scanA(int n) {
    __shared__ int sh[1024];
    int t = threadIdx.x;
    int i = blockIdx.x * 1024 + t;
    sh[t] = (i < n) ? g_cnt[i] : 0;
    __syncthreads();
#pragma unroll
    for (int d = 512; d > 0; d >>= 1) {
        if (t < d) sh[t] += sh[t + d];
        __syncthreads();
    }
    if (t == 0) g_blksum[blockIdx.x] = sh[0];
}
__global__ void k_scanB(int nb) {
    __shared__ int sh[128];
    int t = threadIdx.x;
    int v = (t < nb) ? g_blksum[t] : 0;
    sh[t] = v;
    __syncthreads();
#pragma unroll
    for (int d = 1; d < 128; d <<= 1) {
        int u = 0;
        if (t >= d) u = sh[t - d];
        __syncthreads();
        if (t >= d) sh[t] += u;
        __syncthreads();
    }
    if (t < nb) g_blkoff[t] = sh[t] - v;
}
__global__ void k_scanC(int n) {
    __shared__ int sh[1024];
    int t = threadIdx.x;
    int i = blockIdx.x * 1024 + t;
    int c = (i < n) ? g_cnt[i] : 0;
    sh[t] = c;
    __syncthreads();
#pragma unroll
    for (int d = 1; d < 1024; d <<= 1) {
        int u = 0;
        if (t >= d) u = sh[t - d];
        __syncthreads();
        if (t >= d) sh[t] += u;
        __syncthreads();
    }
    if (i < n) {
        int off = g_blkoff[blockIdx.x] + sh[t] - c;
        g_off[i] = off;
        g_dis[i] = rsqrtf((float)(c + 1));
        if (i == n - 1) g_off[n] = off + c;
    }
}
__global__ void k_scatter(const int* __restrict__ ei, int E) {
    int e = blockIdx.x * blockDim.x + threadIdx.x;
    int is64 = g_is64;
    if (e < E) {
        int s = load_idx(ei, e, is64);
        int d = load_idx(ei, (long long)E + e, is64);
        int p = g_off[d] + atomicAdd(&g_cur[d], 1);
        g_esrc[p] = s;
        g_enrm[p] = g_dis[s] * g_dis[d];
    }
}

// --------------- weight conversions (fp32 -> fp16, transposed) --------------
__global__ void k_wconv(const float* __restrict__ W1) {
    int i = blockIdx.x * blockDim.x + threadIdx.x;
    if (i < FIN * HID) {
        int k = i / HID, n = i % HID;
        g_w1h[(size_t)n * FIN + k] = __float2half_rn(W1[i]);
    }
}
__global__ void k_wconv2(const float* __restrict__ W2) {
    int i = blockIdx.x * blockDim.x + threadIdx.x;
    if (i < HID * NCLS) {
        int k = i / NCLS, n = i % NCLS;
        g_w2t[(size_t)n * HID + k] = __float2half_rn(W2[i]);
    }
}

// ---------- GEMM1 via mma.sync fp16: [N,512] x [512,128] -> g_h1f ----------
// CTA tile 128x128, K chunks of 32. 8 warps: warp tile 32(M) x 64(N). 1 term.
#define SA 40   // smem stride in halves (conflict-free fragment reads)

__global__ __launch_bounds__(256) void k_gemm1_mma(const float* __restrict__ X, int M) {
    __shared__ __half sA[128 * SA];
    __shared__ __half sB[128 * SA];

    int t    = threadIdx.x;
    int lane = t & 31;
    int wid  = t >> 5;
    int wm   = wid & 3;   // 0..3 : M groups of 32
    int wn   = wid >> 2;  // 0..1 : N groups of 64
    int blockRow = blockIdx.x * 128;

    float acc[2][8][4];
#pragma unroll
    for (int mi = 0; mi < 2; mi++)
#pragma unroll
        for (int ni = 0; ni < 8; ni++)
#pragma unroll
            for (int c = 0; c < 4; c++) acc[mi][ni][c] = 0.f;

    const int lg = lane >> 2;          // 0..7
    const int lk = (lane & 3) * 2;     // 0,2,4,6

    for (int ch = 0; ch < 16; ch++) {
        int kt = ch * 32;
        // A fill: 128 rows x 32 k, fp32 -> fp16
#pragma unroll
        for (int i = 0; i < 4; i++) {
            int f  = t + i * 256;
            int r  = f >> 3;
            int c4 = f & 7;
            int gr = blockRow + r;
            if (gr >= M) gr = M - 1;
            float4 v = *(const float4*)&X[(size_t)gr * FIN + kt + c4 * 4];
            ull h = (ull)pack_h2(v.x, v.y) | ((ull)pack_h2(v.z, v.w) << 32);
            *(ull*)&sA[r * SA + c4 * 4] = h;
        }
        // B fill: 128 n-rows x 32 k
#pragma unroll
        for (int i = 0; i < 4; i++) {
            int f  = t + i * 256;
            int n  = f >> 3;
            int c4 = f & 7;
            *(ull*)&sB[n * SA + c4 * 4] = *(const ull*)&g_w1h[(size_t)n * FIN + kt + c4 * 4];
        }
        __syncthreads();

#pragma unroll
        for (int kk = 0; kk < 2; kk++) {
            int k0 = kk * 16 + lk;
            uint32_t ah[2][4];
#pragma unroll
            for (int mi = 0; mi < 2; mi++) {
                int r0 = wm * 32 + mi * 16 + lg;
                ah[mi][0] = *(const uint32_t*)&sA[r0 * SA + k0];
                ah[mi][1] = *(const uint32_t*)&sA[(r0 + 8) * SA + k0];
                ah[mi][2] = *(const uint32_t*)&sA[r0 * SA + k0 + 8];
                ah[mi][3] = *(const uint32_t*)&sA[(r0 + 8) * SA + k0 + 8];
            }
#pragma unroll
            for (int ni = 0; ni < 8; ni++) {
                int c0 = wn * 64 + ni * 8 + lg;
                uint32_t b0 = *(const uint32_t*)&sB[c0 * SA + k0];
                uint32_t b1 = *(const uint32_t*)&sB[c0 * SA + k0 + 8];
#pragma unroll
                for (int mi = 0; mi < 2; mi++)
                    MMA_F16(acc[mi][ni], ah[mi], b0, b1);
            }
        }
        __syncthreads();
    }

#pragma unroll
    for (int mi = 0; mi < 2; mi++) {
        int r0 = blockRow + wm * 32 + mi * 16 + (lane >> 2);
#pragma unroll
        for (int ni = 0; ni < 8; ni++) {
            int c2 = (wn * 64 + ni * 8 + (lane & 3) * 2) >> 1;
            if (r0 < M)
                g_h1f[(size_t)r0 * (HID / 2) + c2] = __floats2half2_rn(acc[mi][ni][0], acc[mi][ni][1]);
            if (r0 + 8 < M)
                g_h1f[(size_t)(r0 + 8) * (HID / 2) + c2] = __floats2half2_rn(acc[mi][ni][2], acc[mi][ni][3]);
        }
    }
}

// ------------- Aggregation 1: warp per node, fp16 gather, fp16 out ---------
__global__ void k_agg1(const float* __restrict__ b1, int n) {
    int w = (blockIdx.x * blockDim.x + threadIdx.x) >> 5;
    if (w >= n) return;
    int l = threadIdx.x & 31;

    float di = g_dis[w];
    float dself = di * di;

    const __half2* self = &g_h1f[(size_t)w * (HID / 2) + l * 2];
    float2 s0 = __half22float2(self[0]);
    float2 s1 = __half22float2(self[1]);
    float4 acc = make_float4(s0.x * dself, s0.y * dself, s1.x * dself, s1.y * dself);

    int beg = g_off[w], end = g_off[w + 1];
    for (int p = beg; p < end; p++) {
        int   s  = g_esrc[p];
        float wt = g_enrm[p];
        uint2 v = *(const uint2*)&g_h1f[(size_t)s * (HID / 2) + l * 2];
        float2 f0 = u32_as_f2h(v.x);
        float2 f1 = u32_as_f2h(v.y);
        acc.x = fmaf(f0.x, wt, acc.x);
        acc.y = fmaf(f0.y, wt, acc.y);
        acc.z = fmaf(f1.x, wt, acc.z);
        acc.w = fmaf(f1.y, wt, acc.w);
    }
    float4 bb = *(const float4*)&b1[l * 4];
    acc.x = fmaxf(acc.x + bb.x, 0.f);
    acc.y = fmaxf(acc.y + bb.y, 0.f);
    acc.z = fmaxf(acc.z + bb.z, 0.f);
    acc.w = fmaxf(acc.w + bb.w, 0.f);
    uint2 o;
    o.x = pack_h2(acc.x, acc.y);
    o.y = pack_h2(acc.z, acc.w);
    *(uint2*)&g_a1f[(size_t)w * (HID / 2) + l * 2] = o;
}

// ---------- GEMM2 via mma.sync fp16: [N,128] x [128,40] -> g_h2f ----------
// CTA tile 128 rows; 8 warps x 16 rows. Whole W2^T resident in smem.
#define SB2 136  // B smem stride in halves; bank = (4*lg + lane&3) all-distinct

__global__ __launch_bounds__(256) void k_gemm2_mma(int M) {
    __shared__ __half sA[128 * SA];
    __shared__ __half sB[NCLS * SB2];

    int t    = threadIdx.x;
    int lane = t & 31;
    int wid  = t >> 5;
    int blockRow = blockIdx.x * 128;

    float acc[5][4];
#pragma unroll
    for (int ni = 0; ni < 5; ni++)
#pragma unroll
        for (int c = 0; c < 4; c++) acc[ni][c] = 0.f;

    // load whole W2^T (40 x 128 halves) once
    for (int i = t; i < NCLS * (HID / 4); i += 256) {
        int n = i / (HID / 4);
        int q = i % (HID / 4);
        *(ull*)&sB[n * SB2 + q * 4] = *(const ull*)&g_w2t[(size_t)n * HID + q * 4];
    }

    const int lg = lane >> 2;
    const int lk = (lane & 3) * 2;
    const __half* a1 = (const __half*)g_a1f;

    for (int ch = 0; ch < 4; ch++) {
        int kt = ch * 32;
        // A fill: 128 rows x 32 halves (already fp16)
#pragma unroll
        for (int i = 0; i < 4; i++) {
            int f  = t + i * 256;
            int r  = f >> 3;
            int c4 = f & 7;
            int gr = blockRow + r;
            if (gr >= M) gr = M - 1;
            *(ull*)&sA[r * SA + c4 * 4] = *(const ull*)&a1[(size_t)gr * HID + kt + c4 * 4];
        }
        __syncthreads();

#pragma unroll
        for (int kk = 0; kk < 2; kk++) {
            int k0 = kk * 16 + lk;
            int r0 = wid * 16 + lg;
            uint32_t a[4];
            a[0] = *(const uint32_t*)&sA[r0 * SA + k0];
            a[1] = *(const uint32_t*)&sA[(r0 + 8) * SA + k0];
            a[2] = *(const uint32_t*)&sA[r0 * SA + k0 + 8];
            a[3] = *(const uint32_t*)&sA[(r0 + 8) * SA + k0 + 8];
            int kb = kt + kk * 16 + lk;
#pragma unroll
            for (int ni = 0; ni < 5; ni++) {
                int c0 = ni * 8 + lg;
                uint32_t b0 = *(const uint32_t*)&sB[c0 * SB2 + kb];
                uint32_t b1 = *(const uint32_t*)&sB[c0 * SB2 + kb + 8];
                MMA_F16(acc[ni], a, b0, b1);
            }
        }
        __syncthreads();
    }

    int r0 = blockRow + wid * 16 + (lane >> 2);
#pragma unroll
    for (int ni = 0; ni < 5; ni++) {
        int c2 = (ni * 8 + (lane & 3) * 2) >> 1;
        if (r0 < M)
            g_h2f[(size_t)r0 * (NCLS / 2) + c2] = __floats2half2_rn(acc[ni][0], acc[ni][1]);
        if (r0 + 8 < M)
            g_h2f[(size_t)(r0 + 8) * (NCLS / 2) + c2] = __floats2half2_rn(acc[ni][2], acc[ni][3]);
    }
}

// ------- Aggregation 2 + bias + log_softmax: warp per node, fp16 gather ----
__global__ void k_agg2(const float* __restrict__ b2, float* __restrict__ out, int n) {
    int w = (blockIdx.x * blockDim.x + threadIdx.x) >> 5;
    if (w >= n) return;
    int l = threadIdx.x & 31;
    bool act = (l < NCLS / 2);   // lanes 0..19 handle col pairs

    float di = g_dis[w];
    float dself = di * di;

    float2 acc = make_float2(0.f, 0.f);
    if (act) {
        float2 f = __half22float2(g_h2f[(size_t)w * (NCLS / 2) + l]);
        acc.x = f.x * dself;
        acc.y = f.y * dself;
    }

    int beg = g_off[w], end = g_off[w + 1];
    for (int p = beg; p < end; p++) {
        int   s  = g_esrc[p];
        float wt = g_enrm[p];
        if (act) {
            float2 f = __half22float2(g_h2f[(size_t)s * (NCLS / 2) + l]);
            acc.x = fmaf(f.x, wt, acc.x);
            acc.y = fmaf(f.y, wt, acc.y);
        }
    }
    if (act) {
        acc.x += b2[2 * l];
        acc.y += b2[2 * l + 1];
    }

    float m = act ? fmaxf(acc.x, acc.y) : -1e30f;
#pragma unroll
    for (int o = 16; o >= 1; o >>= 1) m = fmaxf(m, __shfl_xor_sync(0xffffffffu, m, o));
    float e = act ? (expf(acc.x - m) + expf(acc.y - m)) : 0.f;
#pragma unroll
    for (int o = 16; o >= 1; o >>= 1) e += __shfl_xor_sync(0xffffffffu, e, o);
    float lse = m + logf(e);

    if (act) {
        out[(size_t)w * NCLS + 2 * l]     = acc.x - lse;
        out[(size_t)w * NCLS + 2 * l + 1] = acc.y - lse;
    }
}

// --------------------------------- launch ----------------------------------
// gemm1 stays at launch #4 (the slot the profiler captures).
extern "C" void kernel_launch(void* const* d_in, const int* in_sizes, int n_in,
                              void* d_out, int out_size) {
    const float* x  = (const float*)d_in[0];
    const int*   ei = (const int*)d_in[1];
    const float* W1 = (const float*)d_in[2];
    const float* b1 = (const float*)d_in[3];
    const float* W2 = (const float*)d_in[4];
    const float* b2 = (const float*)d_in[5];
    float*       out = (float*)d_out;

    int N = in_sizes[0] / FIN;       // 100000
    int E = in_sizes[1] / 2;         // 1600000
    int nb = (N + 1023) / 1024;

    k_wconv<<<(FIN * HID + 255) / 256, 256>>>(W1);          // 1
    k_probe<<<1, 1>>>((const unsigned*)d_in[1]);            // 2
    k_init<<<(N + 255) / 256, 256>>>(N);                    // 3
    k_gemm1_mma<<<(N + 127) / 128, 256>>>(x, N);            // 4  <- profiled
    k_wconv2<<<(HID * NCLS + 255) / 256, 256>>>(W2);        // 5
    k_hist<<<(E + 255) / 256, 256>>>(ei, E);                // 6
    k_scanA<<<nb, 1024>>>(N);                               // 7
    k_scanB<<<1, 128>>>(nb);                                // 8
    k_scanC<<<nb, 1024>>>(N);                               // 9
    k_scatter<<<(E + 255) / 256, 256>>>(ei, E);             // 10
    k_agg1<<<(N * 32 + 255) / 256, 256>>>(b1, N);           // 11
    k_gemm2_mma<<<(N + 127) / 128, 256>>>(N);               // 12
    k_agg2<<<(N * 32 + 255) / 256, 256>>>(b2, out, N);      // 13
}